// round 1
// baseline (speedup 1.0000x reference)
#include <cuda_runtime.h>
#include <math.h>

#define NV 1024
#define NB 16
#define EGOS_PER_BLOCK 32
#define SLOTS 4
#define THREADS (EGOS_PER_BLOCK * SLOTS)

__global__ __launch_bounds__(THREADS)
void rulepolicy_kernel(const float* __restrict__ state,
                       const float* __restrict__ lengths,
                       const float* __restrict__ v0p,
                       const float* __restrict__ s0p,
                       const float* __restrict__ dthp,
                       const float* __restrict__ amaxp,
                       const float* __restrict__ bp,
                       float* __restrict__ out)
{
    // Staged candidate data for this batch: x, y, cos(psi), sin(psi) packed; v separate.
    __shared__ float4 cand[NV];
    __shared__ float  cv[NV];

    const int bat = blockIdx.y;
    const int t = threadIdx.x;
    const float* st = state + bat * (NV * 5);

    // Stage all 1024 vehicles of this batch into shared memory.
    for (int i = t; i < NV; i += THREADS) {
        float x   = st[i * 5 + 0];
        float y   = st[i * 5 + 1];
        float v   = st[i * 5 + 2];
        float psi = st[i * 5 + 3];
        float sp, cp;
        sincosf(psi, &sp, &cp);
        cand[i] = make_float4(x, y, cp, sp);
        cv[i] = v;
    }
    __syncthreads();

    const int jl   = blockIdx.x * EGOS_PER_BLOCK + (t >> 2);  // ego vehicle index
    const int slot = t & 3;

    const float4 ego = cand[jl];
    const float  vj  = cv[jl];
    const float xj = ego.x, yj = ego.y, cj = ego.z, sj = ego.w;

    // cos^2(20 deg), cos(45 deg)
    const float C20SQ = 0.8830222215594891f;
    const float C45   = 0.7071067811865476f;
    const float INF   = __int_as_float(0x7f800000);

    float best = INF;
    int   bidx = 0;
    int   stopi = 0;

    #pragma unroll 4
    for (int i = slot; i < NV; i += SLOTS) {
        float4 c = cand[i];
        float dx = c.x - xj;
        float dy = c.y - yj;
        float r2 = fmaf(dx, dx, dy * dy);
        float nd = fmaf(dx, cj, dy * sj);        // = dr * cos(delpsi)
        float n2 = nd * nd;
        bool ahead = nd > 0.0f;
        // valid leader: ndist>0 and |delpsi|<20deg  <=>  n2 > r2*cos^2(20)
        bool valid = ahead && (n2 > r2 * C20SQ);
        if (valid && nd < best) { best = nd; bidx = i; }
        // stop condition: dr<20 & |delpsi|<60 & |dpsi|>45 & v_i>v_j
        float cpd = fmaf(c.z, cj, c.w * sj);     // cos(psi_i - psi_j)
        bool sc = (r2 < 400.0f) && ahead && (n2 > 0.25f * r2)
                  && (cpd < C45) && (cv[i] > vj);
        stopi |= (int)sc;
    }

    // Reduce across the 4 slots of this ego (in-warp quad).
    #pragma unroll
    for (int m = 1; m <= 2; m <<= 1) {
        float ob = __shfl_xor_sync(0xFFFFFFFFu, best, m);
        int   oi = __shfl_xor_sync(0xFFFFFFFFu, bidx, m);
        int   os = __shfl_xor_sync(0xFFFFFFFFu, stopi, m);
        // first-occurrence argmin semantics: tie -> smaller index
        if (ob < best || (ob == best && oi < bidx)) { best = ob; bidx = oi; }
        stopi |= os;
    }

    if (slot == 0) {
        const float V0 = v0p[0], S0 = s0p[0], DTH = dthp[0];
        const float AMAX = amaxp[0], BB = bp[0];

        float4 ld = cand[bidx];
        float  vl = cv[bidx];
        float dvx = vl * ld.z - vj * cj;
        float dvy = vl * ld.w - vj * sj;
        float ndv = fmaf(dvx, cj, dvy * sj);     // = dv * cos(vdelpsi), exact incl. dv=0

        float sal   = best - lengths[jl];
        float sstar = S0 + vj * DTH + (vj * ndv) / (2.0f * sqrtf(AMAX * BB));
        float q  = vj / V0;
        float q2 = q * q;
        float afree = AMAX * (1.0f - q2 * q2);

        float action;
        if (stopi) {
            action = afree - AMAX;               // ratio = 1
        } else if (isinf(sal) || isnan(sal)) {
            action = afree;
        } else {
            float r = sstar / sal;
            action = afree - AMAX * r * r;
        }
        out[bat * NV + jl] = action;
    }
}

extern "C" void kernel_launch(void* const* d_in, const int* in_sizes, int n_in,
                              void* d_out, int out_size)
{
    const float* state   = (const float*)d_in[0];
    const float* lengths = (const float*)d_in[1];
    const float* v0      = (const float*)d_in[2];
    const float* s0      = (const float*)d_in[3];
    const float* dth     = (const float*)d_in[4];
    const float* amax    = (const float*)d_in[5];
    const float* b       = (const float*)d_in[6];
    float* out = (float*)d_out;

    dim3 grid(NV / EGOS_PER_BLOCK, NB);
    dim3 block(THREADS);
    rulepolicy_kernel<<<grid, block>>>(state, lengths, v0, s0, dth, amax, b, out);
}

// round 2
// speedup vs baseline: 1.0924x; 1.0924x over previous
#include <cuda_runtime.h>
#include <math.h>

#define NV 1024
#define NB 16
#define EGOS_PER_BLOCK 16
#define SLOTS 8
#define THREADS (EGOS_PER_BLOCK * SLOTS)   // 128

// Precomputed per-vehicle SoA: {x, y, cos(psi), sin(psi)} and v.
__device__ float4 g_cand[NB * NV];
__device__ float  g_cv[NB * NV];

__global__ void prep_kernel(const float* __restrict__ state)
{
    int idx = blockIdx.x * blockDim.x + threadIdx.x;   // idx = bat*NV + i
    if (idx >= NB * NV) return;
    const float* s = state + (size_t)idx * 5;          // [B, NV*5] contiguous
    float x = s[0], y = s[1], v = s[2], psi = s[3];
    float sp, cp;
    sincosf(psi, &sp, &cp);
    g_cand[idx] = make_float4(x, y, cp, sp);
    g_cv[idx] = v;
}

__global__ __launch_bounds__(THREADS)
void rulepolicy_kernel(const float* __restrict__ lengths,
                       const float* __restrict__ v0p,
                       const float* __restrict__ s0p,
                       const float* __restrict__ dthp,
                       const float* __restrict__ amaxp,
                       const float* __restrict__ bp,
                       float* __restrict__ out)
{
    __shared__ float4 cand[NV];
    __shared__ float  cv[NV];

    const int bat = blockIdx.y;
    const int t = threadIdx.x;
    const int base = bat * NV;

    // Stage this batch's vehicles (pure coalesced copies; sincos already done).
    for (int i = t; i < NV; i += THREADS) {
        cand[i] = g_cand[base + i];
        cv[i]   = g_cv[base + i];
    }
    __syncthreads();

    const int slot = t & (SLOTS - 1);
    const int jl   = blockIdx.x * EGOS_PER_BLOCK + (t >> 3);

    const float4 ego = cand[jl];
    const float  vj  = cv[jl];
    const float xj = ego.x, yj = ego.y, cj = ego.z, sj = ego.w;

    const float C20SQ = 0.8830222215594891f;   // cos^2(20deg)
    const float C45   = 0.7071067811865476f;   // cos(45deg)
    const float INF   = __int_as_float(0x7f800000);

    float best0 = INF, best1 = INF;
    int   idx0 = 0, idx1 = 0;
    int   stopi = 0;

    #pragma unroll 2
    for (int i = slot; i < NV; i += 2 * SLOTS) {
        float4 ca = cand[i];
        float4 cb = cand[i + SLOTS];

        float dxa = ca.x - xj, dya = ca.y - yj;
        float dxb = cb.x - xj, dyb = cb.y - yj;
        float r2a = fmaf(dxa, dxa, dya * dya);
        float r2b = fmaf(dxb, dxb, dyb * dyb);
        float nda = fmaf(dxa, cj, dya * sj);   // dr * cos(delpsi)
        float ndb = fmaf(dxb, cj, dyb * sj);
        float n2a = nda * nda;
        float n2b = ndb * ndb;

        // Leader: ndist>0 and |delpsi|<20deg  <=>  nd>0 && nd^2 > r2*cos^2(20)
        bool va = (nda > 0.0f) && (n2a > r2a * C20SQ);
        bool vb = (ndb > 0.0f) && (n2b > r2b * C20SQ);
        if (va && nda < best0) { best0 = nda; idx0 = i; }
        if (vb && ndb < best1) { best1 = ndb; idx1 = i + SLOTS; }

        // Stop check only when some lane has a pair within 20m (warp-uniform branch).
        bool near = (r2a < 400.0f) | (r2b < 400.0f);
        if (__ballot_sync(0xFFFFFFFFu, near)) {
            // dr<20 & |delpsi|<60 (=> nd>0 & nd^2>0.25r2) & |dpsi|>45 & v_i>v_j
            float cpda = fmaf(ca.z, cj, ca.w * sj);   // cos(psi_i - psi_j)
            float cpdb = fmaf(cb.z, cj, cb.w * sj);
            bool sca = (r2a < 400.0f) && (nda > 0.0f) && (n2a > 0.25f * r2a)
                       && (cpda < C45) && (cv[i] > vj);
            bool scb = (r2b < 400.0f) && (ndb > 0.0f) && (n2b > 0.25f * r2b)
                       && (cpdb < C45) && (cv[i + SLOTS] > vj);
            stopi |= (int)(sca | scb);
        }
    }

    // Merge dual accumulators (tie -> smaller index).
    float best = best0; int bidx = idx0;
    if (best1 < best || (best1 == best && idx1 < bidx)) { best = best1; bidx = idx1; }

    // Reduce across the 8 slots of this ego (consecutive lanes).
    #pragma unroll
    for (int m = 1; m <= 4; m <<= 1) {
        float ob = __shfl_xor_sync(0xFFFFFFFFu, best, m);
        int   oi = __shfl_xor_sync(0xFFFFFFFFu, bidx, m);
        int   os = __shfl_xor_sync(0xFFFFFFFFu, stopi, m);
        if (ob < best || (ob == best && oi < bidx)) { best = ob; bidx = oi; }
        stopi |= os;
    }

    if (slot == 0) {
        const float V0 = v0p[0], S0 = s0p[0], DTH = dthp[0];
        const float AMAX = amaxp[0], BB = bp[0];

        float4 ld = cand[bidx];
        float  vl = cv[bidx];
        float dvx = vl * ld.z - vj * cj;
        float dvy = vl * ld.w - vj * sj;
        float ndv = fmaf(dvx, cj, dvy * sj);   // dv * cos(vdelpsi), exact incl. dv=0

        float sal   = best - lengths[jl];
        float sstar = S0 + vj * DTH + (vj * ndv) / (2.0f * sqrtf(AMAX * BB));
        float q  = vj / V0;
        float q2 = q * q;
        float afree = AMAX * (1.0f - q2 * q2);

        float action;
        if (stopi) {
            action = afree - AMAX;                     // ratio = 1
        } else if (isinf(sal) || isnan(sal)) {
            action = afree;
        } else {
            float r = sstar / sal;
            action = afree - AMAX * r * r;
        }
        out[bat * NV + jl] = action;
    }
}

extern "C" void kernel_launch(void* const* d_in, const int* in_sizes, int n_in,
                              void* d_out, int out_size)
{
    const float* state   = (const float*)d_in[0];
    const float* lengths = (const float*)d_in[1];
    const float* v0      = (const float*)d_in[2];
    const float* s0      = (const float*)d_in[3];
    const float* dth     = (const float*)d_in[4];
    const float* amax    = (const float*)d_in[5];
    const float* b       = (const float*)d_in[6];
    float* out = (float*)d_out;

    prep_kernel<<<(NB * NV + 255) / 256, 256>>>(state);
    dim3 grid(NV / EGOS_PER_BLOCK, NB);
    rulepolicy_kernel<<<grid, THREADS>>>(lengths, v0, s0, dth, amax, b, out);
}